// round 1
// baseline (speedup 1.0000x reference)
#include <cuda_runtime.h>
#include <math.h>
#include <stdint.h>

// Problem dims
#define BATCH 128
#define TT    512
#define DIM   512
#define HDIM  512
#define ODIM  256
#define NCOL  1536   // 3*HDIM

// Recurrence partition: 4 row-groups x 32 rows; 32 CTAs per group (column slices)
#define NG  4
#define RG  32
#define NC  32
#define NCTA (NG*NC)
#define NTH 256

#define RZ_COLS 32   // pre-activation columns in [0,1024) per CTA
#define XS_COLS 16   // hdim slice of [1024,1536) per CTA
#define XO_COLS 8    // output columns of Wxo per CTA

// Shared memory layout (floats)
#define AST      36          // padded stride for transposed activation tiles (div by 4 -> float4 aligned)
#define ACT_ROWS 768         // 256 (x) + 512 (s)
#define RS_ROWS  512
#define SM_ACT   0
#define SM_RS    (ACT_ROWS*AST)                    // 27648
#define SM_XS    (SM_RS + RS_ROWS*AST)             // +18432
#define SM_RED   (SM_XS + RG*XS_COLS)              // +512
#define SM_TOTAL (SM_RED + 2048)                   // 48640 floats = 194560 bytes

// ---------------- device scratch (static allocation; no cudaMalloc) ----------------
__device__ float g_hV[(size_t)TT * BATCH * NCOL];  // 402 MB precomputed hV[t][b][j]
__device__ float g_s [BATCH * HDIM];
__device__ float g_x [BATCH * ODIM];
__device__ float g_rs[BATCH * HDIM];
__device__ float g_z [BATCH * HDIM];
__device__ unsigned g_bar[NG];

__device__ __forceinline__ float sigf(float x) { return 1.0f / (1.0f + expf(-x)); }

// ---------------- init: zero state, barriers; x0 = H[:, -1, :256] + H[:, -1, 256:512] ----------------
__global__ void init_kernel(const float* __restrict__ H) {
    int i = blockIdx.x * blockDim.x + threadIdx.x;
    if (i < NG) g_bar[i] = 0u;
    if (i < BATCH * HDIM) g_s[i] = 0.0f;
    if (i < BATCH * ODIM) {
        int b = i >> 8, o = i & 255;
        const float* h = H + ((size_t)b * TT + (TT - 1)) * DIM;
        g_x[i] = h[o] + h[o + ODIM];
    }
}

// ---------------- hV GEMM: hV[t][b][j] = sum_d H[b][511-t][d] * Vcat[d][j] ----------------
// grid (12, 512): 12 column tiles of 128, 512 time steps. 256 threads, 8x8 micro.
#define GT_N 128
#define GT_K 8
__global__ void __launch_bounds__(256, 2)
hv_gemm(const float* __restrict__ H,
        const float* __restrict__ Vr,
        const float* __restrict__ Vz,
        const float* __restrict__ Vs) {
    int t  = blockIdx.y;
    int jt = blockIdx.x;
    const float* V = (jt < 4) ? Vr : ((jt < 8) ? Vz : Vs);
    int col0 = (jt & 3) * GT_N;                     // column within the 512-wide V matrix
    const float* A = H + (size_t)(TT - 1 - t) * DIM; // A[b][d] at A + b*(TT*DIM) + d

    __shared__ float Ash[GT_K][BATCH + 4];
    __shared__ float Bsh[GT_K][GT_N];

    int tx = threadIdx.x & 15, ty = threadIdx.x >> 4;
    float acc[8][8];
    #pragma unroll
    for (int i = 0; i < 8; i++)
        #pragma unroll
        for (int jj = 0; jj < 8; jj++) acc[i][jj] = 0.0f;

    for (int k0 = 0; k0 < DIM; k0 += GT_K) {
        for (int i = threadIdx.x; i < BATCH * GT_K; i += 256) {
            int bb = i >> 3, dd = i & 7;
            Ash[dd][bb] = A[(size_t)bb * (TT * DIM) + k0 + dd];
        }
        for (int i = threadIdx.x; i < GT_K * GT_N; i += 256) {
            int dd = i >> 7, jj = i & 127;
            Bsh[dd][jj] = V[(size_t)(k0 + dd) * HDIM + col0 + jj];
        }
        __syncthreads();
        #pragma unroll
        for (int kk = 0; kk < GT_K; kk++) {
            float av[8], bv[8];
            #pragma unroll
            for (int i = 0; i < 4; i++) { av[i] = Ash[kk][ty*4+i]; av[4+i] = Ash[kk][64+ty*4+i]; }
            #pragma unroll
            for (int i = 0; i < 4; i++) { bv[i] = Bsh[kk][tx*4+i]; bv[4+i] = Bsh[kk][64+tx*4+i]; }
            #pragma unroll
            for (int i = 0; i < 8; i++)
                #pragma unroll
                for (int jj = 0; jj < 8; jj++)
                    acc[i][jj] = fmaf(av[i], bv[jj], acc[i][jj]);
        }
        __syncthreads();
    }
    float* outp = g_hV + (size_t)t * BATCH * NCOL + jt * GT_N;
    #pragma unroll
    for (int i = 0; i < 8; i++) {
        int bb = (i < 4) ? (ty*4 + i) : (64 + ty*4 + (i-4));
        #pragma unroll
        for (int jj = 0; jj < 8; jj++) {
            int jc = (jj < 4) ? (tx*4 + jj) : (64 + tx*4 + (jj-4));
            outp[(size_t)bb * NCOL + jc] = acc[i][jj];
        }
    }
}

// ---------------- group barrier: 32 CTAs of one row-group ----------------
__device__ __forceinline__ void group_barrier(int g, unsigned* target) {
    __syncthreads();
    if (threadIdx.x == 0) {
        *target += NC;
        __threadfence();
        atomicAdd(&g_bar[g], 1u);
        volatile unsigned* p = &g_bar[g];
        unsigned tg = *target;
        while (*p < tg) { }
        __threadfence();
    }
    __syncthreads();
}

// ---------------- persistent recurrence kernel: 128 CTAs, 256 threads ----------------
__global__ void __launch_bounds__(NTH, 1)
recur_kernel(const float* __restrict__ W,   // [256][1536]
             const float* __restrict__ Bb,  // [1536]
             const float* __restrict__ U,   // [512][1536]
             const float* __restrict__ Wx,  // [512][768], Wxo = cols [0,256)
             const float* __restrict__ bx,  // [256]
             float* __restrict__ out)       // [128][512][256]
{
    extern __shared__ float sm[];
    float* actT  = sm + SM_ACT;   // [768][36]  transposed activations: rows 0..255 = x, 256..767 = s
    float* rsT   = sm + SM_RS;    // [512][36]  transposed r*s
    float* xs_sh = sm + SM_XS;    // [32][16]
    float* red   = sm + SM_RED;   // reduction scratch

    const int cta = blockIdx.x;
    const int g   = cta >> 5;
    const int c   = cta & 31;
    const int tid = threadIdx.x;
    const int row0 = g * RG;

    const int jrz = c * RZ_COLS;      // this CTA's pre columns in [0,1024)
    const int ks0 = c * XS_COLS;      // this CTA's hdim slice
    const int o0  = c * XO_COLS;      // this CTA's output columns

    unsigned bar_target = 0;

    // Initial staging: x and s (transposed)
    for (int i = tid; i < RG * ODIM; i += NTH) {
        int r = i >> 8, k = i & 255;
        actT[k * AST + r] = g_x[(row0 + r) * ODIM + k];
    }
    for (int i = tid; i < RG * HDIM; i += NTH) {
        int r = i >> 9, k = i & 511;
        actT[(256 + k) * AST + r] = g_s[(row0 + r) * HDIM + k];
    }
    __syncthreads();

    for (int t = 0; t < TT; t++) {
        //==================== PHASE A ====================
        // (A1) rz columns: j = jrz + lane, 4-row blocking. a = x@W + s@U (+bias+hV later)
        {
            int j  = jrz + (tid & 31);
            int r4 = (tid >> 5) * 4;
            float a0 = 0.f, a1 = 0.f, a2 = 0.f, a3 = 0.f;
            const float* wp = W + j;
            #pragma unroll 8
            for (int k = 0; k < ODIM; k++) {
                float w = __ldg(wp + (size_t)k * NCOL);
                float4 av = *(const float4*)(actT + k * AST + r4);
                a0 = fmaf(av.x, w, a0); a1 = fmaf(av.y, w, a1);
                a2 = fmaf(av.z, w, a2); a3 = fmaf(av.w, w, a3);
            }
            const float* up = U + j;
            #pragma unroll 8
            for (int k = 0; k < HDIM; k++) {
                float w = __ldg(up + (size_t)k * NCOL);
                float4 av = *(const float4*)(actT + (256 + k) * AST + r4);
                a0 = fmaf(av.x, w, a0); a1 = fmaf(av.y, w, a1);
                a2 = fmaf(av.z, w, a2); a3 = fmaf(av.w, w, a3);
            }
            float bias = Bb[j];
            const float* hvp = g_hV + ((size_t)t * BATCH + row0 + r4) * NCOL + j;
            float acc[4] = {a0, a1, a2, a3};
            if (j < HDIM) {
                // r gate: store r*s
                #pragma unroll
                for (int q = 0; q < 4; q++) {
                    float a = acc[q] + bias + hvp[(size_t)q * NCOL];
                    float rv = sigf(a);
                    float sval = actT[(256 + j) * AST + (r4 + q)];
                    g_rs[(row0 + r4 + q) * HDIM + j] = rv * sval;
                }
            } else {
                // z gate
                #pragma unroll
                for (int q = 0; q < 4; q++) {
                    float a = acc[q] + bias + hvp[(size_t)q * NCOL];
                    g_z[(row0 + r4 + q) * HDIM + (j - HDIM)] = sigf(a);
                }
            }
        }
        // (A2) xs columns: j = 1024 + ks0 + ks. K=256 over x, 2-way k-split.
        {
            int ks = tid & 15;
            int r4 = ((tid >> 4) & 7) * 4;
            int kq = tid >> 7;      // 0 or 1
            int j  = 1024 + ks0 + ks;
            float a0 = 0.f, a1 = 0.f, a2 = 0.f, a3 = 0.f;
            const float* wp = W + j;
            int kb = kq * 128;
            #pragma unroll 8
            for (int k = kb; k < kb + 128; k++) {
                float w = __ldg(wp + (size_t)k * NCOL);
                float4 av = *(const float4*)(actT + k * AST + r4);
                a0 = fmaf(av.x, w, a0); a1 = fmaf(av.y, w, a1);
                a2 = fmaf(av.z, w, a2); a3 = fmaf(av.w, w, a3);
            }
            if (kq == 1) {
                int slot = tid - 128;
                red[slot*4+0] = a0; red[slot*4+1] = a1; red[slot*4+2] = a2; red[slot*4+3] = a3;
            }
            __syncthreads();
            if (kq == 0) {
                a0 += red[tid*4+0]; a1 += red[tid*4+1]; a2 += red[tid*4+2]; a3 += red[tid*4+3];
                float bias = Bb[j];
                const float* hvp = g_hV + ((size_t)t * BATCH + row0 + r4) * NCOL + j;
                float acc[4] = {a0, a1, a2, a3};
                #pragma unroll
                for (int q = 0; q < 4; q++)
                    xs_sh[(r4 + q) * XS_COLS + ks] = acc[q] + bias + hvp[(size_t)q * NCOL];
            }
        }
        group_barrier(g, &bar_target);   // r*s, z visible group-wide

        //==================== PHASE B ====================
        // stage rsT (transposed) from g_rs
        for (int i = tid; i < RG * HDIM; i += NTH) {
            int r = i >> 9, k = i & 511;
            rsT[k * AST + r] = g_rs[(row0 + r) * HDIM + k];
        }
        __syncthreads();
        // m = (r*s) @ U_s slice; then s_t
        {
            int ks = tid & 15;
            int r4 = ((tid >> 4) & 7) * 4;
            int kq = tid >> 7;      // 0 or 1
            int jcol = 1024 + ks0 + ks;
            float a0 = 0.f, a1 = 0.f, a2 = 0.f, a3 = 0.f;
            const float* up = U + jcol;
            int kb = kq * 256;
            #pragma unroll 8
            for (int k = kb; k < kb + 256; k++) {
                float w = __ldg(up + (size_t)k * NCOL);
                float4 av = *(const float4*)(rsT + k * AST + r4);
                a0 = fmaf(av.x, w, a0); a1 = fmaf(av.y, w, a1);
                a2 = fmaf(av.z, w, a2); a3 = fmaf(av.w, w, a3);
            }
            if (kq == 1) {
                int slot = tid - 128;
                red[slot*4+0] = a0; red[slot*4+1] = a1; red[slot*4+2] = a2; red[slot*4+3] = a3;
            }
            __syncthreads();
            if (kq == 0) {
                a0 += red[tid*4+0]; a1 += red[tid*4+1]; a2 += red[tid*4+2]; a3 += red[tid*4+3];
                int kglob = ks0 + ks;
                float acc[4] = {a0, a1, a2, a3};
                #pragma unroll
                for (int q = 0; q < 4; q++) {
                    int rr = r4 + q;
                    float xs = xs_sh[rr * XS_COLS + ks];
                    float s1 = tanhf(xs + acc[q]);
                    float zv = g_z[(row0 + rr) * HDIM + kglob];
                    float sold = actT[(256 + kglob) * AST + rr];
                    float snew = (1.0f - zv) * sold + zv * s1;
                    g_s[(row0 + rr) * HDIM + kglob] = snew;
                }
            }
        }
        group_barrier(g, &bar_target);   // s_t visible group-wide

        //==================== PHASE C ====================
        // stage s_t (transposed) -> also serves next step's A
        for (int i = tid; i < RG * HDIM; i += NTH) {
            int r = i >> 9, k = i & 511;
            actT[(256 + k) * AST + r] = g_s[(row0 + r) * HDIM + k];
        }
        __syncthreads();
        // x_t = tanh(s_t @ Wxo + bx), 4-way k-split
        {
            int o  = tid & 7;
            int r4 = ((tid >> 3) & 7) * 4;
            int kq = tid >> 6;     // 0..3
            int oc = o0 + o;
            float a0 = 0.f, a1 = 0.f, a2 = 0.f, a3 = 0.f;
            const float* wp = Wx + oc;        // stride 768
            int kb = kq * 128;
            #pragma unroll 8
            for (int k = kb; k < kb + 128; k++) {
                float w = __ldg(wp + (size_t)k * (3 * ODIM));
                float4 av = *(const float4*)(actT + (256 + k) * AST + r4);
                a0 = fmaf(av.x, w, a0); a1 = fmaf(av.y, w, a1);
                a2 = fmaf(av.z, w, a2); a3 = fmaf(av.w, w, a3);
            }
            if (kq > 0) {
                int slot = (kq - 1) * 64 + (tid & 63);
                red[slot*4+0] = a0; red[slot*4+1] = a1; red[slot*4+2] = a2; red[slot*4+3] = a3;
            }
            __syncthreads();
            if (kq == 0) {
                int slot = tid;  // tid < 64 here
                #pragma unroll
                for (int p = 0; p < 3; p++) {
                    a0 += red[(p*64+slot)*4+0]; a1 += red[(p*64+slot)*4+1];
                    a2 += red[(p*64+slot)*4+2]; a3 += red[(p*64+slot)*4+3];
                }
                float bias = bx[oc];
                float acc[4] = {a0, a1, a2, a3};
                #pragma unroll
                for (int q = 0; q < 4; q++) {
                    int rr = r4 + q;
                    float xv = tanhf(acc[q] + bias);
                    g_x[(row0 + rr) * ODIM + oc] = xv;
                    out[((size_t)(row0 + rr) * TT + t) * ODIM + oc] = xv;
                }
            }
        }
        group_barrier(g, &bar_target);   // x_t visible group-wide

        // restage x for next step
        for (int i = tid; i < RG * ODIM; i += NTH) {
            int r = i >> 8, k = i & 255;
            actT[k * AST + r] = g_x[(row0 + r) * ODIM + k];
        }
        __syncthreads();
    }
}

// ---------------- launch ----------------
extern "C" void kernel_launch(void* const* d_in, const int* in_sizes, int n_in,
                              void* d_out, int out_size) {
    const float* H  = (const float*)d_in[0];
    const float* W  = (const float*)d_in[1];
    const float* Bb = (const float*)d_in[2];
    const float* U  = (const float*)d_in[3];
    const float* Wx = (const float*)d_in[4];
    const float* bx = (const float*)d_in[5];
    const float* Vr = (const float*)d_in[6];
    const float* Vz = (const float*)d_in[7];
    const float* Vs = (const float*)d_in[8];
    float* out = (float*)d_out;

    const size_t smem_bytes = (size_t)SM_TOTAL * sizeof(float);  // 194,560 B
    cudaFuncSetAttribute(recur_kernel, cudaFuncAttributeMaxDynamicSharedMemorySize,
                         (int)smem_bytes);

    init_kernel<<<256, 256>>>(H);
    hv_gemm<<<dim3(12, 512), 256>>>(H, Vr, Vz, Vs);
    recur_kernel<<<NCTA, NTH, smem_bytes>>>(W, Bb, U, Wx, bx, out);
}

// round 2
// speedup vs baseline: 1.0319x; 1.0319x over previous
#include <cuda_runtime.h>
#include <math.h>
#include <stdint.h>

// Problem dims
#define BATCH 128
#define TT    512
#define DIM   512
#define HDIM  512
#define ODIM  256
#define NCOL  1536   // 3*HDIM

// Recurrence partition: 4 row-groups x 32 rows; 32 CTAs per group (column slices)
#define NG  4
#define RG  32
#define NC  32
#define NCTA (NG*NC)
#define NTH 256

#define RZ_COLS 32   // pre-activation columns in [0,1024) per CTA
#define XS_COLS 16   // hdim slice of [1024,1536) per CTA
#define XO_COLS 8    // output columns of Wxo per CTA

// Shared memory layout (floats)
#define AST      36          // padded stride for transposed activation tiles (div by 4 -> float4 aligned)
#define ACT_ROWS 768         // 256 (x) + 512 (s)
#define RS_ROWS  512
#define SM_ACT   0
#define SM_RS    (ACT_ROWS*AST)                    // 27648
#define SM_XS    (SM_RS + RS_ROWS*AST)             // +18432
#define SM_RED   (SM_XS + RG*XS_COLS)              // +512
#define SM_TOTAL (SM_RED + 2048)                   // 48640 floats = 194560 bytes

// ---------------- device scratch (static allocation; no cudaMalloc) ----------------
__device__ float g_hV[(size_t)TT * BATCH * NCOL];  // 402 MB precomputed hV[t][b][j]
__device__ float g_s [BATCH * HDIM];
__device__ float g_x [BATCH * ODIM];
__device__ float g_rs[BATCH * HDIM];
__device__ float g_z [BATCH * HDIM];
__device__ unsigned g_bar[NG];

__device__ __forceinline__ float sigf(float x) { return 1.0f / (1.0f + expf(-x)); }

// ---------------- init: zero state, barriers; x0 = H[:, -1, :256] + H[:, -1, 256:512] ----------------
__global__ void init_kernel(const float* __restrict__ H) {
    int i = blockIdx.x * blockDim.x + threadIdx.x;
    if (i < NG) g_bar[i] = 0u;
    if (i < BATCH * HDIM) g_s[i] = 0.0f;
    if (i < BATCH * ODIM) {
        int b = i >> 8, o = i & 255;
        const float* h = H + ((size_t)b * TT + (TT - 1)) * DIM;
        g_x[i] = h[o] + h[o + ODIM];
    }
}

// ---------------- hV GEMM: hV[t][b][j] = sum_d H[b][511-t][d] * Vcat[d][j] ----------------
// grid (12, 512): 12 column tiles of 128, 512 time steps. 256 threads, 8x8 micro.
#define GT_N 128
#define GT_K 8
__global__ void __launch_bounds__(256, 2)
hv_gemm(const float* __restrict__ H,
        const float* __restrict__ Vr,
        const float* __restrict__ Vz,
        const float* __restrict__ Vs) {
    int t  = blockIdx.y;
    int jt = blockIdx.x;
    const float* V = (jt < 4) ? Vr : ((jt < 8) ? Vz : Vs);
    int col0 = (jt & 3) * GT_N;                     // column within the 512-wide V matrix
    const float* A = H + (size_t)(TT - 1 - t) * DIM; // A[b][d] at A + b*(TT*DIM) + d

    __shared__ float Ash[GT_K][BATCH + 4];
    __shared__ float Bsh[GT_K][GT_N];

    int tx = threadIdx.x & 15, ty = threadIdx.x >> 4;
    float acc[8][8];
    #pragma unroll
    for (int i = 0; i < 8; i++)
        #pragma unroll
        for (int jj = 0; jj < 8; jj++) acc[i][jj] = 0.0f;

    for (int k0 = 0; k0 < DIM; k0 += GT_K) {
        for (int i = threadIdx.x; i < BATCH * GT_K; i += 256) {
            int bb = i >> 3, dd = i & 7;
            Ash[dd][bb] = A[(size_t)bb * (TT * DIM) + k0 + dd];
        }
        for (int i = threadIdx.x; i < GT_K * GT_N; i += 256) {
            int dd = i >> 7, jj = i & 127;
            Bsh[dd][jj] = V[(size_t)(k0 + dd) * HDIM + col0 + jj];
        }
        __syncthreads();
        #pragma unroll
        for (int kk = 0; kk < GT_K; kk++) {
            float av[8], bv[8];
            #pragma unroll
            for (int i = 0; i < 4; i++) { av[i] = Ash[kk][ty*4+i]; av[4+i] = Ash[kk][64+ty*4+i]; }
            #pragma unroll
            for (int i = 0; i < 4; i++) { bv[i] = Bsh[kk][tx*4+i]; bv[4+i] = Bsh[kk][64+tx*4+i]; }
            #pragma unroll
            for (int i = 0; i < 8; i++)
                #pragma unroll
                for (int jj = 0; jj < 8; jj++)
                    acc[i][jj] = fmaf(av[i], bv[jj], acc[i][jj]);
        }
        __syncthreads();
    }
    float* outp = g_hV + (size_t)t * BATCH * NCOL + jt * GT_N;
    #pragma unroll
    for (int i = 0; i < 8; i++) {
        int bb = (i < 4) ? (ty*4 + i) : (64 + ty*4 + (i-4));
        #pragma unroll
        for (int jj = 0; jj < 8; jj++) {
            int jc = (jj < 4) ? (tx*4 + jj) : (64 + tx*4 + (jj-4));
            outp[(size_t)bb * NCOL + jc] = acc[i][jj];
        }
    }
}

// ---------------- group barrier: 32 CTAs of one row-group ----------------
__device__ __forceinline__ void group_barrier(int g, unsigned* target) {
    __syncthreads();
    if (threadIdx.x == 0) {
        *target += NC;
        __threadfence();
        atomicAdd(&g_bar[g], 1u);
        volatile unsigned* p = &g_bar[g];
        unsigned tg = *target;
        while (*p < tg) { }
        __threadfence();
    }
    __syncthreads();
}

// ---------------- persistent recurrence kernel: 128 CTAs, 256 threads ----------------
__global__ void __launch_bounds__(NTH, 1)
recur_kernel(const float* __restrict__ W,   // [256][1536]
             const float* __restrict__ Bb,  // [1536]
             const float* __restrict__ U,   // [512][1536]
             const float* __restrict__ Wx,  // [512][768], Wxo = cols [0,256)
             const float* __restrict__ bx,  // [256]
             float* __restrict__ out)       // [128][512][256]
{
    extern __shared__ float sm[];
    float* actT  = sm + SM_ACT;   // [768][36]  transposed activations: rows 0..255 = x, 256..767 = s
    float* rsT   = sm + SM_RS;    // [512][36]  transposed r*s
    float* xs_sh = sm + SM_XS;    // [32][16]
    float* red   = sm + SM_RED;   // reduction scratch

    const int cta = blockIdx.x;
    const int g   = cta >> 5;
    const int c   = cta & 31;
    const int tid = threadIdx.x;
    const int row0 = g * RG;

    const int jrz = c * RZ_COLS;      // this CTA's pre columns in [0,1024)
    const int ks0 = c * XS_COLS;      // this CTA's hdim slice
    const int o0  = c * XO_COLS;      // this CTA's output columns

    unsigned bar_target = 0;

    // Initial staging: x and s (transposed)
    for (int i = tid; i < RG * ODIM; i += NTH) {
        int r = i >> 8, k = i & 255;
        actT[k * AST + r] = g_x[(row0 + r) * ODIM + k];
    }
    for (int i = tid; i < RG * HDIM; i += NTH) {
        int r = i >> 9, k = i & 511;
        actT[(256 + k) * AST + r] = g_s[(row0 + r) * HDIM + k];
    }
    __syncthreads();

    for (int t = 0; t < TT; t++) {
        //==================== PHASE A ====================
        // (A1) rz columns: j = jrz + lane, 4-row blocking. a = x@W + s@U (+bias+hV later)
        {
            int j  = jrz + (tid & 31);
            int r4 = (tid >> 5) * 4;
            float a0 = 0.f, a1 = 0.f, a2 = 0.f, a3 = 0.f;
            const float* wp = W + j;
            #pragma unroll 8
            for (int k = 0; k < ODIM; k++) {
                float w = __ldg(wp + (size_t)k * NCOL);
                float4 av = *(const float4*)(actT + k * AST + r4);
                a0 = fmaf(av.x, w, a0); a1 = fmaf(av.y, w, a1);
                a2 = fmaf(av.z, w, a2); a3 = fmaf(av.w, w, a3);
            }
            const float* up = U + j;
            #pragma unroll 8
            for (int k = 0; k < HDIM; k++) {
                float w = __ldg(up + (size_t)k * NCOL);
                float4 av = *(const float4*)(actT + (256 + k) * AST + r4);
                a0 = fmaf(av.x, w, a0); a1 = fmaf(av.y, w, a1);
                a2 = fmaf(av.z, w, a2); a3 = fmaf(av.w, w, a3);
            }
            float bias = Bb[j];
            const float* hvp = g_hV + ((size_t)t * BATCH + row0 + r4) * NCOL + j;
            float acc[4] = {a0, a1, a2, a3};
            if (j < HDIM) {
                // r gate: store r*s
                #pragma unroll
                for (int q = 0; q < 4; q++) {
                    float a = acc[q] + bias + hvp[(size_t)q * NCOL];
                    float rv = sigf(a);
                    float sval = actT[(256 + j) * AST + (r4 + q)];
                    g_rs[(row0 + r4 + q) * HDIM + j] = rv * sval;
                }
            } else {
                // z gate
                #pragma unroll
                for (int q = 0; q < 4; q++) {
                    float a = acc[q] + bias + hvp[(size_t)q * NCOL];
                    g_z[(row0 + r4 + q) * HDIM + (j - HDIM)] = sigf(a);
                }
            }
        }
        // (A2) xs columns: j = 1024 + ks0 + ks. K=256 over x, 2-way k-split.
        {
            int ks = tid & 15;
            int r4 = ((tid >> 4) & 7) * 4;
            int kq = tid >> 7;      // 0 or 1
            int j  = 1024 + ks0 + ks;
            float a0 = 0.f, a1 = 0.f, a2 = 0.f, a3 = 0.f;
            const float* wp = W + j;
            int kb = kq * 128;
            #pragma unroll 8
            for (int k = kb; k < kb + 128; k++) {
                float w = __ldg(wp + (size_t)k * NCOL);
                float4 av = *(const float4*)(actT + k * AST + r4);
                a0 = fmaf(av.x, w, a0); a1 = fmaf(av.y, w, a1);
                a2 = fmaf(av.z, w, a2); a3 = fmaf(av.w, w, a3);
            }
            if (kq == 1) {
                int slot = tid - 128;
                red[slot*4+0] = a0; red[slot*4+1] = a1; red[slot*4+2] = a2; red[slot*4+3] = a3;
            }
            __syncthreads();
            if (kq == 0) {
                a0 += red[tid*4+0]; a1 += red[tid*4+1]; a2 += red[tid*4+2]; a3 += red[tid*4+3];
                float bias = Bb[j];
                const float* hvp = g_hV + ((size_t)t * BATCH + row0 + r4) * NCOL + j;
                float acc[4] = {a0, a1, a2, a3};
                #pragma unroll
                for (int q = 0; q < 4; q++)
                    xs_sh[(r4 + q) * XS_COLS + ks] = acc[q] + bias + hvp[(size_t)q * NCOL];
            }
        }
        group_barrier(g, &bar_target);   // r*s, z visible group-wide

        //==================== PHASE B ====================
        // stage rsT (transposed) from g_rs
        for (int i = tid; i < RG * HDIM; i += NTH) {
            int r = i >> 9, k = i & 511;
            rsT[k * AST + r] = g_rs[(row0 + r) * HDIM + k];
        }
        __syncthreads();
        // m = (r*s) @ U_s slice; then s_t
        {
            int ks = tid & 15;
            int r4 = ((tid >> 4) & 7) * 4;
            int kq = tid >> 7;      // 0 or 1
            int jcol = 1024 + ks0 + ks;
            float a0 = 0.f, a1 = 0.f, a2 = 0.f, a3 = 0.f;
            const float* up = U + jcol;
            int kb = kq * 256;
            #pragma unroll 8
            for (int k = kb; k < kb + 256; k++) {
                float w = __ldg(up + (size_t)k * NCOL);
                float4 av = *(const float4*)(rsT + k * AST + r4);
                a0 = fmaf(av.x, w, a0); a1 = fmaf(av.y, w, a1);
                a2 = fmaf(av.z, w, a2); a3 = fmaf(av.w, w, a3);
            }
            if (kq == 1) {
                int slot = tid - 128;
                red[slot*4+0] = a0; red[slot*4+1] = a1; red[slot*4+2] = a2; red[slot*4+3] = a3;
            }
            __syncthreads();
            if (kq == 0) {
                a0 += red[tid*4+0]; a1 += red[tid*4+1]; a2 += red[tid*4+2]; a3 += red[tid*4+3];
                int kglob = ks0 + ks;
                float acc[4] = {a0, a1, a2, a3};
                #pragma unroll
                for (int q = 0; q < 4; q++) {
                    int rr = r4 + q;
                    float xs = xs_sh[rr * XS_COLS + ks];
                    float s1 = tanhf(xs + acc[q]);
                    float zv = g_z[(row0 + rr) * HDIM + kglob];
                    float sold = actT[(256 + kglob) * AST + rr];
                    float snew = (1.0f - zv) * sold + zv * s1;
                    g_s[(row0 + rr) * HDIM + kglob] = snew;
                }
            }
        }
        group_barrier(g, &bar_target);   // s_t visible group-wide

        //==================== PHASE C ====================
        // stage s_t (transposed) -> also serves next step's A
        for (int i = tid; i < RG * HDIM; i += NTH) {
            int r = i >> 9, k = i & 511;
            actT[(256 + k) * AST + r] = g_s[(row0 + r) * HDIM + k];
        }
        __syncthreads();
        // x_t = tanh(s_t @ Wxo + bx), 4-way k-split
        {
            int o  = tid & 7;
            int r4 = ((tid >> 3) & 7) * 4;
            int kq = tid >> 6;     // 0..3
            int oc = o0 + o;
            float a0 = 0.f, a1 = 0.f, a2 = 0.f, a3 = 0.f;
            const float* wp = Wx + oc;        // stride 768
            int kb = kq * 128;
            #pragma unroll 8
            for (int k = kb; k < kb + 128; k++) {
                float w = __ldg(wp + (size_t)k * (3 * ODIM));
                float4 av = *(const float4*)(actT + (256 + k) * AST + r4);
                a0 = fmaf(av.x, w, a0); a1 = fmaf(av.y, w, a1);
                a2 = fmaf(av.z, w, a2); a3 = fmaf(av.w, w, a3);
            }
            if (kq > 0) {
                int slot = (kq - 1) * 64 + (tid & 63);
                red[slot*4+0] = a0; red[slot*4+1] = a1; red[slot*4+2] = a2; red[slot*4+3] = a3;
            }
            __syncthreads();
            if (kq == 0) {
                int slot = tid;  // tid < 64 here
                #pragma unroll
                for (int p = 0; p < 3; p++) {
                    a0 += red[(p*64+slot)*4+0]; a1 += red[(p*64+slot)*4+1];
                    a2 += red[(p*64+slot)*4+2]; a3 += red[(p*64+slot)*4+3];
                }
                float bias = bx[oc];
                float acc[4] = {a0, a1, a2, a3};
                #pragma unroll
                for (int q = 0; q < 4; q++) {
                    int rr = r4 + q;
                    float xv = tanhf(acc[q] + bias);
                    g_x[(row0 + rr) * ODIM + oc] = xv;
                    out[((size_t)(row0 + rr) * TT + t) * ODIM + oc] = xv;
                }
            }
        }
        group_barrier(g, &bar_target);   // x_t visible group-wide

        // restage x for next step
        for (int i = tid; i < RG * ODIM; i += NTH) {
            int r = i >> 8, k = i & 255;
            actT[k * AST + r] = g_x[(row0 + r) * ODIM + k];
        }
        __syncthreads();
    }
}

// ---------------- launch ----------------
extern "C" void kernel_launch(void* const* d_in, const int* in_sizes, int n_in,
                              void* d_out, int out_size) {
    const float* H  = (const float*)d_in[0];
    const float* W  = (const float*)d_in[1];
    const float* Bb = (const float*)d_in[2];
    const float* U  = (const float*)d_in[3];
    const float* Wx = (const float*)d_in[4];
    const float* bx = (const float*)d_in[5];
    const float* Vr = (const float*)d_in[6];
    const float* Vz = (const float*)d_in[7];
    const float* Vs = (const float*)d_in[8];
    float* out = (float*)d_out;

    const size_t smem_bytes = (size_t)SM_TOTAL * sizeof(float);  // 194,560 B
    cudaFuncSetAttribute(recur_kernel, cudaFuncAttributeMaxDynamicSharedMemorySize,
                         (int)smem_bytes);

    init_kernel<<<256, 256>>>(H);
    hv_gemm<<<dim3(12, 512), 256>>>(H, Vr, Vz, Vs);
    recur_kernel<<<NCTA, NTH, smem_bytes>>>(W, Bb, U, Wx, bx, out);
}